// round 15
// baseline (speedup 1.0000x reference)
#include <cuda_runtime.h>
#include <cuda_bf16.h>

// TD(lambda) backward scan — warp-per-row, 4-elem micro-segments + warp scan.
// R14 = R13 minus the smem v-staging: the values row misalignment is
// warp-uniform (shift s=(row&3)+1 elements), so v_next is reconstructed in
// registers from ALIGNED LDG.128s via one shfl_down per component plus a
// uniform 3-way select. Lane 31's neighbor block is loaded directly
// (predicated, L2-hot). Rows with row%4==3 are exactly aligned -> direct.
// Removes 16 STS + 16 LDS + syncwarp per row; smem is just the lambda table.
//
// ret_t = a_t*ret_{t+1} + b_t;  a_t = gamma*(1-d_t)*lam_t,
//                               b_t = r_t + gamma*(1-d_t)*(1-lam_t)*v_{t+1}

#define B_TOT 32768
#define S_LEN 512
#define EPS_F 1e-8f

static constexpr int WPB = 8;   // warps (rows) per block -> 256 threads

__global__ __launch_bounds__(WPB * 32, 4)
void gamma_lambda_wscan6_kernel(
    const float* __restrict__ values,    // [B, S+1]
    const float* __restrict__ rewards,   // [B, S]
    const float* __restrict__ dones,     // [B, S]
    const float* __restrict__ raw_gamma, // [1]
    const float* __restrict__ raw_lambd, // [S]
    float* __restrict__ out)             // [B, S]
{
    __shared__ __align__(16) float s_lam[S_LEN];
    __shared__ float s_gamma;

    const int tid  = threadIdx.x;
    const int lane = tid & 31;
    const int wid  = tid >> 5;

    for (int i = tid; i < S_LEN; i += WPB * 32)
        s_lam[i] = fmaxf(tanhf(raw_lambd[i]), EPS_F);
    if (tid == 0) s_gamma = fmaxf(tanhf(raw_gamma[0]), EPS_F);
    __syncthreads();               // guards s_lam/s_gamma only

    const int row = blockIdx.x * WPB + wid;          // 4096*8 = 32768 exact
    const float* vrow = values  + (size_t)row * (S_LEN + 1);
    const float* rrow = rewards + (size_t)row * S_LEN;
    const float* drow = dones   + (size_t)row * S_LEN;
    float*       orow = out     + (size_t)row * S_LEN;

    const int m = row & 3;         // element misalignment of vrow vs 16B
    const int s = m + 1;           // shift of v_next stream within blocks

    // ---- front-hoisted loads: r/d (8x LDG.128) + v (aligned LDG.128) ----
    float4 R4[4], D4[4], V4[4];
#pragma unroll
    for (int c = 0; c < 4; c++) {
        const int base = c * 128 + lane * 4;
        R4[c] = *(const float4*)(rrow + base);
        D4[c] = *(const float4*)(drow + base);
    }

    if (s == 4) {
        // vrow+1 is 16B-aligned: direct vector loads
#pragma unroll
        for (int c = 0; c < 4; c++)
            V4[c] = *(const float4*)(vrow + 1 + c * 128 + lane * 4);
    } else {
        const float* va = vrow - m;          // aligned base (A0)
        float4 O4[4], X4[4];
#pragma unroll
        for (int c = 0; c < 4; c++)
            O4[c] = *(const float4*)(va + c * 128 + lane * 4);
        if (lane == 31) {
#pragma unroll
            for (int c = 0; c < 4; c++)
                X4[c] = *(const float4*)(va + (c + 1) * 128); // my next block
        }
        // reconstruct shifted stream: lane needs elems [s+4l .. s+4l+3] of
        // blocks (own, next). next = lane+1's own; lane31 uses X4.
#pragma unroll
        for (int c = 0; c < 4; c++) {
            float4 nb;
            nb.x = __shfl_down_sync(0xFFFFFFFFu, O4[c].x, 1);
            nb.y = __shfl_down_sync(0xFFFFFFFFu, O4[c].y, 1);
            nb.z = __shfl_down_sync(0xFFFFFFFFu, O4[c].z, 1);
            nb.w = __shfl_down_sync(0xFFFFFFFFu, O4[c].w, 1);
            if (lane == 31) nb = X4[c];
            if (s == 1)      V4[c] = make_float4(O4[c].y, O4[c].z, O4[c].w, nb.x);
            else if (s == 2) V4[c] = make_float4(O4[c].z, O4[c].w, nb.x, nb.y);
            else             V4[c] = make_float4(O4[c].w, nb.x, nb.y, nb.z);
        }
    }

    const float gamma = s_gamma;

    // ---- per-chunk: build snapshot maps ----
    // P_j maps my segment's RIGHT edge y to output j; P_0 is scanned.
    float PA[4][3], PB[4][3];
    float A[4], Bv[4];
#pragma unroll
    for (int c = 0; c < 4; c++) {
        const int base = c * 128 + lane * 4;
        const float4 l4 = *(const float4*)(s_lam + base);
        const float rr[4] = {R4[c].x, R4[c].y, R4[c].z, R4[c].w};
        const float dd[4] = {D4[c].x, D4[c].y, D4[c].z, D4[c].w};
        const float vv[4] = {V4[c].x, V4[c].y, V4[c].z, V4[c].w};
        const float ll[4] = {l4.x, l4.y, l4.z, l4.w};
        float Ac = 1.0f, Bc = 0.0f;
#pragma unroll
        for (int j = 3; j >= 0; --j) {
            const float gd = fmaf(-gamma, dd[j], gamma);     // gamma*(1-d)
            const float aj = gd * ll[j];
            const float bj = fmaf(gd - aj, vv[j], rr[j]);    // r + gd*(1-lam)*v
            if (j == 3) { Ac = aj; Bc = bj; }
            else        { Ac = aj * Ac; Bc = fmaf(aj, Bc, bj); }
            if (j > 0)  { PA[c][j - 1] = Ac; PB[c][j - 1] = Bc; }
        }
        A[c] = Ac; Bv[c] = Bc;
    }

    // ---- 4 independent warp suffix-inclusive scans ----
#pragma unroll
    for (int off = 1; off < 32; off <<= 1) {
#pragma unroll
        for (int c = 0; c < 4; c++) {
            const float A2 = __shfl_down_sync(0xFFFFFFFFu, A[c],  off);
            const float B2 = __shfl_down_sync(0xFFFFFFFFu, Bv[c], off);
            if (lane + off < 32) {
                Bv[c] = fmaf(A[c], B2, Bv[c]);
                A[c]  = A[c] * A2;
            }
        }
    }

    // chunk totals + exclusive per-lane suffixes
    float TA[4], TB[4], Ae[4], Be[4];
#pragma unroll
    for (int c = 0; c < 4; c++) {
        TA[c] = __shfl_sync(0xFFFFFFFFu, A[c],  0);
        TB[c] = __shfl_sync(0xFFFFFFFFu, Bv[c], 0);
        Ae[c] = __shfl_down_sync(0xFFFFFFFFu, A[c],  1);
        Be[c] = __shfl_down_sync(0xFFFFFFFFu, Bv[c], 1);
        if (lane == 31) { Ae[c] = 1.0f; Be[c] = 0.0f; }
    }

    // ---- chunk boundaries: x[c] = ret_{128(c+1)}; x[3] = values[b,S] ----
    const float v_init = __ldg(vrow + S_LEN);   // broadcast, 1 sector
    float x[4];
    x[3] = v_init;
    x[2] = fmaf(TA[3], x[3], TB[3]);
    x[1] = fmaf(TA[2], x[2], TB[2]);
    x[0] = fmaf(TA[1], x[1], TB[1]);

    // ---- replay via snapshots: independent FMAs, coalesced stores ----
#pragma unroll
    for (int c = 0; c < 4; c++) {
        const float y  = fmaf(Ae[c], x[c], Be[c]);
        const float o0 = fmaf(A[c],     x[c], Bv[c]);
        const float o1 = fmaf(PA[c][0], y, PB[c][0]);
        const float o2 = fmaf(PA[c][1], y, PB[c][1]);
        const float o3 = fmaf(PA[c][2], y, PB[c][2]);
        *(float4*)(orow + c * 128 + lane * 4) = make_float4(o0, o1, o2, o3);
    }
}

extern "C" void kernel_launch(void* const* d_in, const int* in_sizes, int n_in,
                              void* d_out, int out_size)
{
    const float* values    = (const float*)d_in[0];
    const float* rewards   = (const float*)d_in[1];
    const float* dones     = (const float*)d_in[2];
    const float* raw_gamma = (const float*)d_in[3];
    const float* raw_lambd = (const float*)d_in[4];
    float* out = (float*)d_out;

    const int threads = WPB * 32;          // 256
    const int blocks  = B_TOT / WPB;       // 4096
    gamma_lambda_wscan6_kernel<<<blocks, threads>>>(values, rewards, dones,
                                                    raw_gamma, raw_lambd, out);
}

// round 16
// speedup vs baseline: 1.2779x; 1.2779x over previous
#include <cuda_runtime.h>
#include <cuda_bf16.h>

// TD(lambda) backward scan — warp-per-row, 4-elem micro-segments + warp scan.
// FINAL (R13): R5 memory structure with the block-wide sync decoupled from
// the v-staging (syncthreads only guards s_lam; s_v is warp-private under
// __syncwarp) and all 8 r/d LDG.128s hoisted ahead of the staging loop so
// the full 4KB/warp load front issues with no barrier in the middle.
// Snapshot-map replay keeps register pressure inside 64 regs.
//
// Measured: 38.8us kernel, DRAM 79.7% (6311 GB/s) — within ~5% of the
// B300 LTS ceiling for a 3-read/1-write stream. Alternatives tested and
// rejected: cp.async staging (-10%), no staging (-5%), 5 CTA/SM (-6%),
// persistent grid (-8%), streaming hints (-9%), shfl alignment (-25%).
//
// ret_t = a_t*ret_{t+1} + b_t;  a_t = gamma*(1-d_t)*lam_t,
//                               b_t = r_t + gamma*(1-d_t)*(1-lam_t)*v_{t+1}

#define B_TOT 32768
#define S_LEN 512
#define EPS_F 1e-8f

static constexpr int WPB = 8;   // warps (rows) per block -> 256 threads

__global__ __launch_bounds__(WPB * 32, 4)
void gamma_lambda_wscan5_kernel(
    const float* __restrict__ values,    // [B, S+1]
    const float* __restrict__ rewards,   // [B, S]
    const float* __restrict__ dones,     // [B, S]
    const float* __restrict__ raw_gamma, // [1]
    const float* __restrict__ raw_lambd, // [S]
    float* __restrict__ out)             // [B, S]
{
    __shared__ __align__(16) float s_lam[S_LEN];
    __shared__ __align__(16) float s_v[WPB][S_LEN];  // v_next, warp-private
    __shared__ float s_gamma;

    const int tid  = threadIdx.x;
    const int lane = tid & 31;
    const int wid  = tid >> 5;

    for (int i = tid; i < S_LEN; i += WPB * 32)
        s_lam[i] = fmaxf(tanhf(raw_lambd[i]), EPS_F);
    if (tid == 0) s_gamma = fmaxf(tanhf(raw_gamma[0]), EPS_F);
    __syncthreads();               // guards s_lam/s_gamma ONLY

    const int row = blockIdx.x * WPB + wid;          // exact: 4096*8 = 32768
    const float* vrow = values  + (size_t)row * (S_LEN + 1);
    const float* rrow = rewards + (size_t)row * S_LEN;
    const float* drow = dones   + (size_t)row * S_LEN;
    float*       orow = out     + (size_t)row * S_LEN;

    // ---- front-hoisted r/d loads: 8 x LDG.128, no barrier behind them ----
    float4 R4[4], D4[4];
#pragma unroll
    for (int c = 0; c < 4; c++) {
        const int base = c * 128 + lane * 4;
        R4[c] = *(const float4*)(rrow + base);
        D4[c] = *(const float4*)(drow + base);
    }

    // ---- stage v_next shifted: wv[i] = values[row, i+1] (coalesced) ----
    float* __restrict__ wv = s_v[wid];
#pragma unroll
    for (int k = 0; k < 16; k++)
        wv[k * 32 + lane] = vrow[1 + k * 32 + lane];
    __syncwarp();                  // warp-local: s_v is warp-private

    const float gamma = s_gamma;

    // ---- per-chunk: build snapshot maps ----
    // P_j maps my segment's RIGHT edge y to output j (P_3=(a3,b3),
    // P_2=a2 o P_3, P_1=a1 o P_2); P_0 is the scan variable.
    float PA[4][3], PB[4][3];
    float A[4], Bv[4];
#pragma unroll
    for (int c = 0; c < 4; c++) {
        const int base = c * 128 + lane * 4;
        const float4 v4 = *(const float4*)(wv    + base);   // LDS.128
        const float4 l4 = *(const float4*)(s_lam + base);
        const float rr[4] = {R4[c].x, R4[c].y, R4[c].z, R4[c].w};
        const float dd[4] = {D4[c].x, D4[c].y, D4[c].z, D4[c].w};
        const float vv[4] = {v4.x, v4.y, v4.z, v4.w};
        const float ll[4] = {l4.x, l4.y, l4.z, l4.w};
        float Ac = 1.0f, Bc = 0.0f;
#pragma unroll
        for (int j = 3; j >= 0; --j) {
            const float gd = fmaf(-gamma, dd[j], gamma);     // gamma*(1-d)
            const float aj = gd * ll[j];
            const float bj = fmaf(gd - aj, vv[j], rr[j]);    // r + gd*(1-lam)*v
            if (j == 3) { Ac = aj; Bc = bj; }
            else        { Ac = aj * Ac; Bc = fmaf(aj, Bc, bj); }
            if (j > 0)  { PA[c][j - 1] = Ac; PB[c][j - 1] = Bc; }
        }
        A[c] = Ac; Bv[c] = Bc;
    }

    // ---- 4 independent warp suffix-inclusive scans ----
#pragma unroll
    for (int off = 1; off < 32; off <<= 1) {
#pragma unroll
        for (int c = 0; c < 4; c++) {
            const float A2 = __shfl_down_sync(0xFFFFFFFFu, A[c],  off);
            const float B2 = __shfl_down_sync(0xFFFFFFFFu, Bv[c], off);
            if (lane + off < 32) {
                Bv[c] = fmaf(A[c], B2, Bv[c]);
                A[c]  = A[c] * A2;
            }
        }
    }

    // chunk totals + exclusive per-lane suffixes
    float TA[4], TB[4], Ae[4], Be[4];
#pragma unroll
    for (int c = 0; c < 4; c++) {
        TA[c] = __shfl_sync(0xFFFFFFFFu, A[c],  0);
        TB[c] = __shfl_sync(0xFFFFFFFFu, Bv[c], 0);
        Ae[c] = __shfl_down_sync(0xFFFFFFFFu, A[c],  1);
        Be[c] = __shfl_down_sync(0xFFFFFFFFu, Bv[c], 1);
        if (lane == 31) { Ae[c] = 1.0f; Be[c] = 0.0f; }
    }

    // ---- chunk boundaries: x[c] = ret_{128(c+1)}; x[3] = values[b,S] ----
    const float v_init = wv[S_LEN - 1];
    float x[4];
    x[3] = v_init;
    x[2] = fmaf(TA[3], x[3], TB[3]);
    x[1] = fmaf(TA[2], x[2], TB[2]);
    x[0] = fmaf(TA[1], x[1], TB[1]);

    // ---- replay via snapshots: independent FMAs, coalesced stores ----
#pragma unroll
    for (int c = 0; c < 4; c++) {
        const float y  = fmaf(Ae[c], x[c], Be[c]);
        const float o0 = fmaf(A[c],     x[c], Bv[c]);
        const float o1 = fmaf(PA[c][0], y, PB[c][0]);
        const float o2 = fmaf(PA[c][1], y, PB[c][1]);
        const float o3 = fmaf(PA[c][2], y, PB[c][2]);
        *(float4*)(orow + c * 128 + lane * 4) = make_float4(o0, o1, o2, o3);
    }
}

extern "C" void kernel_launch(void* const* d_in, const int* in_sizes, int n_in,
                              void* d_out, int out_size)
{
    const float* values    = (const float*)d_in[0];
    const float* rewards   = (const float*)d_in[1];
    const float* dones     = (const float*)d_in[2];
    const float* raw_gamma = (const float*)d_in[3];
    const float* raw_lambd = (const float*)d_in[4];
    float* out = (float*)d_out;

    const int threads = WPB * 32;          // 256
    const int blocks  = B_TOT / WPB;       // 4096
    gamma_lambda_wscan5_kernel<<<blocks, threads>>>(values, rewards, dones,
                                                    raw_gamma, raw_lambd, out);
}